// round 2
// baseline (speedup 1.0000x reference)
#include <cuda_runtime.h>
#include <math.h>

// ---------------- problem constants ----------------
constexpr int Bn   = 4;
constexpr int Tn   = 2048;
constexpr int Fn   = 1024;
constexpr int Cn   = 200;
constexpr int Hn   = 8;
constexpr int DFFn = 128;
constexpr int Ln   = 2;
constexpr int Sn   = Tn + Cn;         // 2248
constexpr int DH   = Fn / Hn;         // 128

constexpr long SF = (long)Sn * Fn;    // per-batch token*feature stride

// ---------------- scratch (device globals; no allocations allowed) ----------
__device__ float g_src[(long)Bn * Sn * Fn];
__device__ float g_Q  [(long)Bn * Sn * Fn];
__device__ float g_K  [(long)Bn * Sn * Fn];
__device__ float g_V  [(long)Bn * Sn * Fn];
__device__ float g_ao [(long)Bn * Sn * Fn];   // attention out
__device__ float g_t  [(long)Bn * Sn * Fn];   // proj / ffn out
__device__ float g_ff [(long)Bn * Sn * DFFn];
__device__ float g_wc [(long)2 * Ln * Fn * Fn];   // fused QK weights
__device__ float g_bc [(long)2 * Ln * Fn];        // fused QK biases

// ---------------- small reduction helpers ----------------
__inline__ __device__ float warpSum(float v) {
    #pragma unroll
    for (int o = 16; o; o >>= 1) v += __shfl_xor_sync(0xFFFFFFFFu, v, o);
    return v;
}

// ---------------- build src = concat(x, prototypes-as-(F,C)-view) -----------
__global__ void build_src_kernel(const float* __restrict__ x,
                                 const float* __restrict__ proto,
                                 float* __restrict__ src) {
    long i = (long)blockIdx.x * 256 + threadIdx.x;
    const long total = (long)Bn * Sn * Fn;
    if (i >= total) return;
    int f  = (int)(i % Fn);
    long bs = i / Fn;
    int s  = (int)(bs % Sn);
    int b  = (int)(bs / Sn);
    float v;
    if (s < Tn)  v = x[((long)b * Tn + s) * Fn + f];
    else         v = proto[(long)f * Cn + (s - Tn)];   // view(1,F,-1) reshape
    src[i] = v;
}

// ---------------- generic tiled GEMM ----------------
// C[m,n] = act( alpha * sum_k A[m,k] * B(k,n) + bias[n] )
// TRANSB=true : B is (N,K) row-major (weights)  -> B(k,n) = B[n*ldb + k]
// TRANSB=false: B is (K,N) row-major            -> B(k,n) = B[k*ldb + n]
#define BM 64
#define BN 64
#define BK 16

template<bool TRANSB, int ACT>
__global__ __launch_bounds__(256)
void gemm_kernel(const float* __restrict__ A, const float* __restrict__ Bm,
                 const float* __restrict__ bias, float* __restrict__ C,
                 int M, int N, int K, int lda, int ldb, int ldc) {
    __shared__ float As[BK][BM];
    __shared__ float Bs[BK][BN + 1];

    const int rowBlock = blockIdx.y * BM;
    const int colBlock = blockIdx.x * BN;
    const int tx = threadIdx.x, ty = threadIdx.y;
    const int tid = ty * 16 + tx;

    float acc[4][4] = {};

    for (int k0 = 0; k0 < K; k0 += BK) {
        #pragma unroll
        for (int i = tid; i < BM * BK; i += 256) {
            int m = i / BK, k = i % BK;
            int gm = rowBlock + m, gk = k0 + k;
            As[k][m] = (gm < M && gk < K) ? A[(long)gm * lda + gk] : 0.f;
        }
        if (TRANSB) {
            #pragma unroll
            for (int i = tid; i < BN * BK; i += 256) {
                int n = i / BK, k = i % BK;
                int gn = colBlock + n, gk = k0 + k;
                Bs[k][n] = (gn < N && gk < K) ? Bm[(long)gn * ldb + gk] : 0.f;
            }
        } else {
            #pragma unroll
            for (int i = tid; i < BN * BK; i += 256) {
                int k = i / BN, n = i % BN;
                int gk = k0 + k, gn = colBlock + n;
                Bs[k][n] = (gk < K && gn < N) ? Bm[(long)gk * ldb + gn] : 0.f;
            }
        }
        __syncthreads();
        #pragma unroll
        for (int k = 0; k < BK; k++) {
            float av[4], bv[4];
            #pragma unroll
            for (int i = 0; i < 4; i++) av[i] = As[k][ty * 4 + i];
            #pragma unroll
            for (int j = 0; j < 4; j++) bv[j] = Bs[k][tx * 4 + j];
            #pragma unroll
            for (int i = 0; i < 4; i++)
                #pragma unroll
                for (int j = 0; j < 4; j++)
                    acc[i][j] += av[i] * bv[j];
        }
        __syncthreads();
    }
    #pragma unroll
    for (int i = 0; i < 4; i++) {
        int gm = rowBlock + ty * 4 + i;
        if (gm >= M) continue;
        #pragma unroll
        for (int j = 0; j < 4; j++) {
            int gn = colBlock + tx * 4 + j;
            if (gn >= N) continue;
            float v = acc[i][j];
            if (bias) v += bias[gn];
            if (ACT == 1) v = fmaxf(v, 0.f);
            C[(long)gm * ldc + gn] = v;
        }
    }
}

// ---------------- fused bias: bc[m] = ib[m] + sum_j IW[m,j]*bq[j] ----------
__global__ __launch_bounds__(256)
void bias_comb_kernel(const float* __restrict__ IW, const float* __restrict__ bq,
                      const float* __restrict__ ib, float* __restrict__ bc) {
    int row  = blockIdx.x * 8 + (threadIdx.x >> 5);
    int lane = threadIdx.x & 31;
    float s = 0.f;
    for (int j = lane; j < Fn; j += 32) s += IW[(long)row * Fn + j] * bq[j];
    s = warpSum(s);
    if (lane == 0) bc[row] = s + ib[row];
}

// ---------------- flash attention (fp32, 64x64 tiles, dh=128) ---------------
constexpr int FBM = 64;
constexpr int FBN = 64;
constexpr int KT  = (Sn + FBN - 1) / FBN;     // 36
constexpr int KSLD = 129;                      // padded K/V smem row stride
constexpr int SCLD = 65;                       // score smem row stride
constexpr int FLASH_SMEM = (FBM * 128 + FBN * KSLD + FBM * SCLD + 3 * FBM) * 4;

__global__ __launch_bounds__(256)
void flash_kernel(const float* __restrict__ Q, const float* __restrict__ K,
                  const float* __restrict__ V, float* __restrict__ O) {
    extern __shared__ float sm[];
    float* Qs = sm;                       // [64][128]
    float* Ks = Qs + FBM * 128;           // [64][129], reused for V
    float* Sc = Ks + FBN * KSLD;          // [64][65]
    float* mS = Sc + FBM * SCLD;          // [64]
    float* lS = mS + FBM;
    float* cS = lS + FBM;

    const int qt = blockIdx.x;
    const int bh = blockIdx.y;
    const int b  = bh / Hn, h = bh % Hn;
    const int tid = threadIdx.x;
    const int tx = tid & 15, ty = tid >> 4;
    const float scale = 0.08838834764831843f;   // 1/sqrt(128)

    const long base = (long)b * SF + (long)h * DH;
    const int  q0   = qt * FBM;

    // load Q tile (rows beyond S -> 0)
    for (int i = tid; i < FBM * DH; i += 256) {
        int r = i >> 7, d = i & 127;
        int s = q0 + r;
        Qs[r * 128 + d] = (s < Sn) ? Q[base + (long)s * Fn + d] : 0.f;
    }
    if (tid < FBM) { mS[tid] = -1e30f; lS[tid] = 0.f; }

    float acc[4][8] = {};

    for (int kt = 0; kt < KT; kt++) {
        const int k0 = kt * FBN;
        __syncthreads();                      // prev PV done, Ks reusable
        // load K tile
        for (int i = tid; i < FBN * DH; i += 256) {
            int r = i >> 7, d = i & 127;
            int s = k0 + r;
            Ks[r * KSLD + d] = (s < Sn) ? K[base + (long)s * Fn + d] : 0.f;
        }
        __syncthreads();

        // scores: rows ty*4+i, cols j*16+tx  (conflict-free Ks reads)
        float sc[4][4] = {};
        #pragma unroll 4
        for (int k = 0; k < DH; k++) {
            float av[4], bv[4];
            #pragma unroll
            for (int i = 0; i < 4; i++) av[i] = Qs[(ty * 4 + i) * 128 + k];
            #pragma unroll
            for (int j = 0; j < 4; j++) bv[j] = Ks[(j * 16 + tx) * KSLD + k];
            #pragma unroll
            for (int i = 0; i < 4; i++)
                #pragma unroll
                for (int j = 0; j < 4; j++)
                    sc[i][j] += av[i] * bv[j];
        }
        #pragma unroll
        for (int i = 0; i < 4; i++)
            #pragma unroll
            for (int j = 0; j < 4; j++) {
                int col = j * 16 + tx;
                Sc[(ty * 4 + i) * SCLD + col] =
                    (k0 + col < Sn) ? sc[i][j] * scale : -1e30f;
            }
        __syncthreads();

        // online softmax stats: 4 threads per row
        {
            int row = tid >> 2, qq = tid & 3;
            float vals[16];
            float mloc = -1e30f;
            #pragma unroll
            for (int c = 0; c < 16; c++) {
                vals[c] = Sc[row * SCLD + qq * 16 + c];
                mloc = fmaxf(mloc, vals[c]);
            }
            mloc = fmaxf(mloc, __shfl_xor_sync(0xFFFFFFFFu, mloc, 1));
            mloc = fmaxf(mloc, __shfl_xor_sync(0xFFFFFFFFu, mloc, 2));
            float mOld = mS[row];
            float mNew = fmaxf(mOld, mloc);
            float ssum = 0.f;
            #pragma unroll
            for (int c = 0; c < 16; c++) {
                float p = __expf(vals[c] - mNew);
                Sc[row * SCLD + qq * 16 + c] = p;
                ssum += p;
            }
            ssum += __shfl_xor_sync(0xFFFFFFFFu, ssum, 1);
            ssum += __shfl_xor_sync(0xFFFFFFFFu, ssum, 2);
            if (qq == 0) {
                float corr = __expf(mOld - mNew);
                cS[row] = corr;
                lS[row] = lS[row] * corr + ssum;
                mS[row] = mNew;
            }
        }
        // load V tile into Ks (scores already consumed into Sc)
        for (int i = tid; i < FBN * DH; i += 256) {
            int r = i >> 7, d = i & 127;
            int s = k0 + r;
            Ks[r * KSLD + d] = (s < Sn) ? V[base + (long)s * Fn + d] : 0.f;
        }
        __syncthreads();

        // rescale + PV accumulate: acc rows ty*4+i, cols j*16+tx
        #pragma unroll
        for (int i = 0; i < 4; i++) {
            float corr = cS[ty * 4 + i];
            #pragma unroll
            for (int j = 0; j < 8; j++) acc[i][j] *= corr;
        }
        #pragma unroll 2
        for (int k = 0; k < FBN; k++) {
            float pv[4], vv[8];
            #pragma unroll
            for (int i = 0; i < 4; i++) pv[i] = Sc[(ty * 4 + i) * SCLD + k];
            #pragma unroll
            for (int j = 0; j < 8; j++) vv[j] = Ks[k * KSLD + j * 16 + tx];
            #pragma unroll
            for (int i = 0; i < 4; i++)
                #pragma unroll
                for (int j = 0; j < 8; j++)
                    acc[i][j] += pv[i] * vv[j];
        }
    }

    // write output: O[b, s, h*128 + col]
    #pragma unroll
    for (int i = 0; i < 4; i++) {
        int row = ty * 4 + i;
        int s = q0 + row;
        if (s >= Sn) continue;
        float inv = 1.f / lS[row];
        #pragma unroll
        for (int j = 0; j < 8; j++) {
            O[base + (long)s * Fn + j * 16 + tx] = acc[i][j] * inv;
        }
    }
}

// ---------------- fused residual add + LayerNorm (F = 1024 = 256*4) ---------
__global__ __launch_bounds__(256)
void add_ln_kernel(float* __restrict__ src, const float* __restrict__ res,
                   const float* __restrict__ g, const float* __restrict__ bta) {
    long row = blockIdx.x;
    float* p = src + row * (long)Fn;
    const float* q = res + row * (long)Fn;
    int tid = threadIdx.x;
    int w = tid >> 5, lane = tid & 31;

    float v[4];
    float s = 0.f, s2 = 0.f;
    #pragma unroll
    for (int i = 0; i < 4; i++) {
        int f = tid + i * 256;
        float t = p[f] + q[f];
        v[i] = t;
        s += t;
        s2 += t * t;
    }
    __shared__ float sh0[8], sh1[8], bmean, brstd;
    s = warpSum(s); s2 = warpSum(s2);
    if (lane == 0) { sh0[w] = s; sh1[w] = s2; }
    __syncthreads();
    if (w == 0) {
        float a  = lane < 8 ? sh0[lane] : 0.f;
        float b2 = lane < 8 ? sh1[lane] : 0.f;
        a = warpSum(a); b2 = warpSum(b2);
        if (lane == 0) {
            float mean = a * (1.f / Fn);
            float var  = b2 * (1.f / Fn) - mean * mean;
            bmean = mean;
            brstd = rsqrtf(var + 1e-5f);
        }
    }
    __syncthreads();
    float mean = bmean, rstd = brstd;
    #pragma unroll
    for (int i = 0; i < 4; i++) {
        int f = tid + i * 256;
        p[f] = (v[i] - mean) * rstd * g[f] + bta[f];
    }
}

// ---------------- conv head: out[b,f,t] = relu(bias[f] + sum src*W) ---------
__global__ __launch_bounds__(256)
void conv_kernel(const float* __restrict__ src, const float* __restrict__ W,
                 const float* __restrict__ bias, float* __restrict__ out) {
    int b = blockIdx.z;
    const float* Sp = src + (long)b * SF;
    float* O = out + (long)b * Fn * Tn;

    __shared__ float As[16][64];
    __shared__ float Bs[16][65];

    const int fBlock = blockIdx.y * 64;
    const int tBlock = blockIdx.x * 64;
    const int tx = threadIdx.x, ty = threadIdx.y;
    const int tid = ty * 16 + tx;
    const int Kc = 3 * Fn;

    float acc[4][4] = {};

    for (int k0 = 0; k0 < Kc; k0 += 16) {
        #pragma unroll
        for (int i = tid; i < 64 * 16; i += 256) {
            int m = i / 16, k = i % 16;
            As[k][m] = W[(long)(fBlock + m) * Kc + k0 + k];
        }
        #pragma unroll
        for (int i = tid; i < 64 * 16; i += 256) {
            int n = i / 16, k = i % 16;
            int kk = k0 + k;
            int fi = kk / 3, tap = kk % 3;
            int t = tBlock + n + tap - 1;
            Bs[k][n] = (t >= 0 && t < Tn) ? Sp[(long)t * Fn + fi] : 0.f;
        }
        __syncthreads();
        #pragma unroll
        for (int k = 0; k < 16; k++) {
            float av[4], bv[4];
            #pragma unroll
            for (int i = 0; i < 4; i++) av[i] = As[k][ty * 4 + i];
            #pragma unroll
            for (int j = 0; j < 4; j++) bv[j] = Bs[k][tx * 4 + j];
            #pragma unroll
            for (int i = 0; i < 4; i++)
                #pragma unroll
                for (int j = 0; j < 4; j++)
                    acc[i][j] += av[i] * bv[j];
        }
        __syncthreads();
    }
    #pragma unroll
    for (int i = 0; i < 4; i++) {
        int f = fBlock + ty * 4 + i;
        #pragma unroll
        for (int j = 0; j < 4; j++) {
            int t = tBlock + tx * 4 + j;
            O[(long)f * Tn + t] = fmaxf(acc[i][j] + bias[f], 0.f);
        }
    }
}

// ---------------- host driver ----------------
static inline int cdiv(int a, int b) { return (a + b - 1) / b; }

extern "C" void kernel_launch(void* const* d_in, const int* in_sizes, int n_in,
                              void* d_out, int out_size) {
    const float* x     = (const float*)d_in[0];
    const float* proto = (const float*)d_in[1];
    const float* wq    = (const float*)d_in[2];
    const float* bq    = (const float*)d_in[3];
    const float* wk    = (const float*)d_in[4];
    const float* bk    = (const float*)d_in[5];
    const float* in_w  = (const float*)d_in[6];
    const float* in_b  = (const float*)d_in[7];
    const float* out_w = (const float*)d_in[8];
    const float* out_b = (const float*)d_in[9];
    const float* l1_w  = (const float*)d_in[10];
    const float* l1_b  = (const float*)d_in[11];
    const float* l2_w  = (const float*)d_in[12];
    const float* l2_b  = (const float*)d_in[13];
    const float* ln1_g = (const float*)d_in[14];
    const float* ln1_b = (const float*)d_in[15];
    const float* ln2_g = (const float*)d_in[16];
    const float* ln2_b = (const float*)d_in[17];
    const float* emb_w = (const float*)d_in[18];
    const float* emb_b = (const float*)d_in[19];
    float* out = (float*)d_out;

    float *src, *Q, *K, *V, *ao, *tp, *ff, *wc, *bc;
    cudaGetSymbolAddress((void**)&src, g_src);
    cudaGetSymbolAddress((void**)&Q,   g_Q);
    cudaGetSymbolAddress((void**)&K,   g_K);
    cudaGetSymbolAddress((void**)&V,   g_V);
    cudaGetSymbolAddress((void**)&ao,  g_ao);
    cudaGetSymbolAddress((void**)&tp,  g_t);
    cudaGetSymbolAddress((void**)&ff,  g_ff);
    cudaGetSymbolAddress((void**)&wc,  g_wc);
    cudaGetSymbolAddress((void**)&bc,  g_bc);

    static bool attr_done = false;
    if (!attr_done) {
        cudaFuncSetAttribute(flash_kernel,
                             cudaFuncAttributeMaxDynamicSharedMemorySize,
                             FLASH_SMEM);
        attr_done = true;
    }

    const int BS = Bn * Sn;                       // 8992 rows
    const dim3 blk(16, 16);
    const long FF = (long)Fn * Fn;

    // 0) build src
    {
        long total = (long)Bn * Sn * Fn;
        build_src_kernel<<<(unsigned)((total + 255) / 256), 256>>>(x, proto, src);
    }

    // 1) fuse q/k convs into in-projections: Wc = IW_{q|k} @ W_{q|k}
    for (int l = 0; l < Ln; l++) {
        const float* IW  = in_w + (long)l * 3 * FF;
        const float* IB  = in_b + (long)l * 3 * Fn;
        dim3 g(cdiv(Fn, BN), cdiv(Fn, BM), 1);
        gemm_kernel<false, 0><<<g, blk>>>(IW, wq + (long)l * FF, nullptr,
                                          wc + (long)(2 * l) * FF,
                                          Fn, Fn, Fn, Fn, Fn, Fn);
        gemm_kernel<false, 0><<<g, blk>>>(IW + FF, wk + (long)l * FF, nullptr,
                                          wc + (long)(2 * l + 1) * FF,
                                          Fn, Fn, Fn, Fn, Fn, Fn);
        bias_comb_kernel<<<Fn / 8, 256>>>(IW, bq + (long)l * Fn, IB,
                                          bc + (long)(2 * l) * Fn);
        bias_comb_kernel<<<Fn / 8, 256>>>(IW + FF, bk + (long)l * Fn, IB + Fn,
                                          bc + (long)(2 * l + 1) * Fn);
    }

    for (int l = 0; l < Ln; l++) {
        const float* IW  = in_w + (long)l * 3 * FF;
        const float* IB  = in_b + (long)l * 3 * Fn;
        const float* OW  = out_w + (long)l * FF;
        const float* OB  = out_b + (long)l * Fn;
        const float* W1  = l1_w + (long)l * DFFn * Fn;
        const float* B1  = l1_b + (long)l * DFFn;
        const float* W2  = l2_w + (long)l * Fn * DFFn;
        const float* B2  = l2_b + (long)l * Fn;

        dim3 gFF(cdiv(Fn, BN), cdiv(BS, BM), 1);

        // Q = src @ WcQ^T + bcQ  (fused conv_q + in-proj-q)
        gemm_kernel<true, 0><<<gFF, blk>>>(src, wc + (long)(2 * l) * FF,
                                           bc + (long)(2 * l) * Fn, Q,
                                           BS, Fn, Fn, Fn, Fn, Fn);
        // K = src @ WcK^T + bcK
        gemm_kernel<true, 0><<<gFF, blk>>>(src, wc + (long)(2 * l + 1) * FF,
                                           bc + (long)(2 * l + 1) * Fn, K,
                                           BS, Fn, Fn, Fn, Fn, Fn);
        // V = src @ IW_v^T + ib_v
        gemm_kernel<true, 0><<<gFF, blk>>>(src, IW + 2 * FF, IB + 2 * Fn, V,
                                           BS, Fn, Fn, Fn, Fn, Fn);

        // flash attention -> ao
        {
            dim3 g(KT, Bn * Hn);
            flash_kernel<<<g, 256, FLASH_SMEM>>>(Q, K, V, ao);
        }

        // out-proj: tp = ao @ OW^T + OB
        gemm_kernel<true, 0><<<gFF, blk>>>(ao, OW, OB, tp, BS, Fn, Fn, Fn, Fn, Fn);
        // src = LN(src + tp)
        add_ln_kernel<<<BS, 256>>>(src, tp, ln1_g + (long)l * Fn, ln1_b + (long)l * Fn);

        // ffn1: ff = relu(src @ W1^T + B1)
        {
            dim3 g(cdiv(DFFn, BN), cdiv(BS, BM), 1);
            gemm_kernel<true, 1><<<g, blk>>>(src, W1, B1, ff, BS, DFFn, Fn,
                                             Fn, Fn, DFFn);
        }
        // ffn2: tp = ff @ W2^T + B2
        gemm_kernel<true, 0><<<gFF, blk>>>(ff, W2, B2, tp, BS, Fn, DFFn,
                                           DFFn, DFFn, Fn);
        // src = LN(src + tp)
        add_ln_kernel<<<BS, 256>>>(src, tp, ln2_g + (long)l * Fn, ln2_b + (long)l * Fn);
    }

    // conv head -> out (B, F, T), ReLU
    {
        dim3 g(cdiv(Tn, 64), cdiv(Fn, 64), Bn);
        conv_kernel<<<g, blk>>>(src, emb_w, emb_b, out);
    }
    (void)in_sizes; (void)n_in; (void)out_size;
}

// round 3
// speedup vs baseline: 3.2879x; 3.2879x over previous
#include <cuda_runtime.h>
#include <math.h>

// ---------------- problem constants ----------------
constexpr int Bn   = 4;
constexpr int Tn   = 2048;
constexpr int Fn   = 1024;
constexpr int Cn   = 200;
constexpr int Hn   = 8;
constexpr int DFFn = 128;
constexpr int Ln   = 2;
constexpr int Sn   = Tn + Cn;         // 2248
constexpr int DH   = Fn / Hn;         // 128

constexpr long SF = (long)Sn * Fn;    // per-batch token*feature stride

// ---------------- scratch (device globals; no allocations allowed) ----------
__device__ float g_src[(long)Bn * Sn * Fn];
__device__ float g_Q  [(long)Bn * Sn * Fn];
__device__ float g_K  [(long)Bn * Sn * Fn];
__device__ float g_V  [(long)Bn * Sn * Fn];
__device__ float g_ao [(long)Bn * Sn * Fn];   // attention out
__device__ float g_t  [(long)Bn * Sn * Fn];   // proj / ffn out
__device__ float g_ff [(long)Bn * Sn * DFFn];
__device__ float g_wc [(long)2 * Ln * Fn * Fn];   // fused QK weights
__device__ float g_bc [(long)2 * Ln * Fn];        // fused QK biases

// ---------------- helpers ----------------
__inline__ __device__ float warpSum(float v) {
    #pragma unroll
    for (int o = 16; o; o >>= 1) v += __shfl_xor_sync(0xFFFFFFFFu, v, o);
    return v;
}
__device__ __forceinline__ unsigned f2tf(float f) {
    unsigned u;
    asm("cvt.rna.tf32.f32 %0, %1;" : "=r"(u) : "f"(f));
    return u;
}
__device__ __forceinline__ void mma_tf32(float c[4],
        unsigned a0, unsigned a1, unsigned a2, unsigned a3,
        unsigned b0, unsigned b1) {
    asm volatile(
        "mma.sync.aligned.m16n8k8.row.col.f32.tf32.tf32.f32 "
        "{%0,%1,%2,%3}, {%4,%5,%6,%7}, {%8,%9}, {%0,%1,%2,%3};"
        : "+f"(c[0]), "+f"(c[1]), "+f"(c[2]), "+f"(c[3])
        : "r"(a0), "r"(a1), "r"(a2), "r"(a3), "r"(b0), "r"(b1));
}

// ---------------- build src = concat(x, prototypes-as-(F,C)-view) -----------
__global__ void build_src_kernel(const float* __restrict__ x,
                                 const float* __restrict__ proto,
                                 float* __restrict__ src) {
    long i = (long)blockIdx.x * 256 + threadIdx.x;
    const long total = (long)Bn * Sn * Fn;
    if (i >= total) return;
    int f  = (int)(i % Fn);
    long bs = i / Fn;
    int s  = (int)(bs % Sn);
    int b  = (int)(bs / Sn);
    float v;
    if (s < Tn)  v = x[((long)b * Tn + s) * Fn + f];
    else         v = proto[(long)f * Cn + (s - Tn)];   // view(1,F,-1) reshape
    src[i] = v;
}

// =============== TF32 mma GEMM: 128x128x32 tiles, 8 warps ====================
// C[m,n] = act( sum_k A[m,k]*B(k,n) + bias[n] )
// TRANSB=true : B is (N,K) row-major. TRANSB=false: B is (K,N) row-major.
// N and K must be multiples of 32 (holds for all call sites). M predicated.
constexpr int GLD = 36;   // smem word stride; bank = (4r + c) & 31

template<bool TRANSB, int ACT>
__global__ __launch_bounds__(256)
void gemm_mma_kernel(const float* __restrict__ A, const float* __restrict__ Bm,
                     const float* __restrict__ bias, float* __restrict__ C,
                     int M, int N, int K, int lda, int ldb, int ldc) {
    __shared__ unsigned As[128 * GLD];
    __shared__ unsigned Bs[128 * GLD];

    const int tid = threadIdx.x;
    const int w = tid >> 5, lane = tid & 31;
    const int qr = lane >> 2, qc = lane & 3;
    const int wm = (w & 3) * 32;          // warp row offset (2 m-frags)
    const int wn = (w >> 2) * 64;         // warp col offset (8 n-frags)
    const int m0 = blockIdx.y * 128;
    const int n0 = blockIdx.x * 128;

    float acc[2][8][4] = {};

    for (int k0 = 0; k0 < K; k0 += 32) {
        // ---- A tile fill (float4, rows predicated) ----
        {
            int c = (tid & 7) * 4;
            #pragma unroll
            for (int r = tid >> 3; r < 128; r += 32) {
                int gm = m0 + r;
                float4 v = {0.f, 0.f, 0.f, 0.f};
                if (gm < M) v = *(const float4*)(A + (long)gm * lda + k0 + c);
                unsigned* p = &As[r * GLD + c];
                p[0] = f2tf(v.x); p[1] = f2tf(v.y);
                p[2] = f2tf(v.z); p[3] = f2tf(v.w);
            }
        }
        // ---- B tile fill: Bs[n][k] ----
        if (TRANSB) {
            int c = (tid & 7) * 4;
            #pragma unroll
            for (int r = tid >> 3; r < 128; r += 32) {
                int gn = n0 + r;
                float4 v = {0.f, 0.f, 0.f, 0.f};
                if (gn < N) v = *(const float4*)(Bm + (long)gn * ldb + k0 + c);
                unsigned* p = &Bs[r * GLD + c];
                p[0] = f2tf(v.x); p[1] = f2tf(v.y);
                p[2] = f2tf(v.z); p[3] = f2tf(v.w);
            }
        } else {
            for (int i = tid; i < 128 * 32; i += 256) {
                int k = i >> 7, n = i & 127;
                int gn = n0 + n, gk = k0 + k;
                float v = (gn < N) ? Bm[(long)gk * ldb + gn] : 0.f;
                Bs[n * GLD + k] = f2tf(v);
            }
        }
        __syncthreads();
        // ---- mma mainloop ----
        #pragma unroll
        for (int kk = 0; kk < 32; kk += 8) {
            unsigned af[2][4], bf[8][2];
            #pragma unroll
            for (int i = 0; i < 2; i++) {
                int r = wm + i * 16;
                af[i][0] = As[(r + qr)     * GLD + kk + qc];
                af[i][1] = As[(r + qr + 8) * GLD + kk + qc];
                af[i][2] = As[(r + qr)     * GLD + kk + qc + 4];
                af[i][3] = As[(r + qr + 8) * GLD + kk + qc + 4];
            }
            #pragma unroll
            for (int j = 0; j < 8; j++) {
                int n = wn + j * 8;
                bf[j][0] = Bs[(n + qr) * GLD + kk + qc];
                bf[j][1] = Bs[(n + qr) * GLD + kk + qc + 4];
            }
            #pragma unroll
            for (int i = 0; i < 2; i++)
                #pragma unroll
                for (int j = 0; j < 8; j++)
                    mma_tf32(acc[i][j], af[i][0], af[i][1], af[i][2], af[i][3],
                             bf[j][0], bf[j][1]);
        }
        __syncthreads();
    }
    // ---- epilogue ----
    #pragma unroll
    for (int i = 0; i < 2; i++) {
        #pragma unroll
        for (int j = 0; j < 8; j++) {
            int col = n0 + wn + j * 8 + 2 * qc;
            float bsum = bias ? bias[col]     : 0.f;
            float bsu1 = bias ? bias[col + 1] : 0.f;
            #pragma unroll
            for (int h = 0; h < 2; h++) {
                int row = m0 + wm + i * 16 + qr + h * 8;
                if (row >= M) continue;
                float v0 = acc[i][j][h * 2 + 0] + bsum;
                float v1 = acc[i][j][h * 2 + 1] + bsu1;
                if (ACT == 1) { v0 = fmaxf(v0, 0.f); v1 = fmaxf(v1, 0.f); }
                float2 pr = {v0, v1};
                *(float2*)(C + (long)row * ldc + col) = pr;
            }
        }
    }
}

// =============== conv head as TF32 mma GEMM ================================
// out[b,f,t] = relu(bias[f] + sum_{k=fi*3+tap} W[f,k] * src[b, t+tap-1, fi])
__global__ __launch_bounds__(256)
void conv_mma_kernel(const float* __restrict__ src, const float* __restrict__ W,
                     const float* __restrict__ bias, float* __restrict__ out) {
    __shared__ unsigned As[128 * GLD];
    __shared__ unsigned Bs[128 * GLD];

    const int b = blockIdx.z;
    const float* Sp = src + (long)b * SF;
    float* O = out + (long)b * Fn * Tn;

    const int tid = threadIdx.x;
    const int w = tid >> 5, lane = tid & 31;
    const int qr = lane >> 2, qc = lane & 3;
    const int wm = (w & 3) * 32;
    const int wn = (w >> 2) * 64;
    const int m0 = blockIdx.y * 128;     // f
    const int n0 = blockIdx.x * 128;     // t
    const int Kc = 3 * Fn;

    float acc[2][8][4] = {};

    for (int k0 = 0; k0 < Kc; k0 += 32) {
        {
            int c = (tid & 7) * 4;
            #pragma unroll
            for (int r = tid >> 3; r < 128; r += 32) {
                float4 v = *(const float4*)(W + (long)(m0 + r) * Kc + k0 + c);
                unsigned* p = &As[r * GLD + c];
                p[0] = f2tf(v.x); p[1] = f2tf(v.y);
                p[2] = f2tf(v.z); p[3] = f2tf(v.w);
            }
        }
        for (int i = tid; i < 128 * 32; i += 256) {
            int k = i >> 7, n = i & 127;
            int kk = k0 + k;
            int fi = kk / 3, tap = kk % 3;
            int t = n0 + n + tap - 1;
            float v = (t >= 0 && t < Tn) ? Sp[(long)t * Fn + fi] : 0.f;
            Bs[n * GLD + k] = f2tf(v);
        }
        __syncthreads();
        #pragma unroll
        for (int kk = 0; kk < 32; kk += 8) {
            unsigned af[2][4], bf[8][2];
            #pragma unroll
            for (int i = 0; i < 2; i++) {
                int r = wm + i * 16;
                af[i][0] = As[(r + qr)     * GLD + kk + qc];
                af[i][1] = As[(r + qr + 8) * GLD + kk + qc];
                af[i][2] = As[(r + qr)     * GLD + kk + qc + 4];
                af[i][3] = As[(r + qr + 8) * GLD + kk + qc + 4];
            }
            #pragma unroll
            for (int j = 0; j < 8; j++) {
                int n = wn + j * 8;
                bf[j][0] = Bs[(n + qr) * GLD + kk + qc];
                bf[j][1] = Bs[(n + qr) * GLD + kk + qc + 4];
            }
            #pragma unroll
            for (int i = 0; i < 2; i++)
                #pragma unroll
                for (int j = 0; j < 8; j++)
                    mma_tf32(acc[i][j], af[i][0], af[i][1], af[i][2], af[i][3],
                             bf[j][0], bf[j][1]);
        }
        __syncthreads();
    }
    #pragma unroll
    for (int i = 0; i < 2; i++) {
        #pragma unroll
        for (int j = 0; j < 8; j++) {
            int col = n0 + wn + j * 8 + 2 * qc;
            #pragma unroll
            for (int h = 0; h < 2; h++) {
                int row = m0 + wm + i * 16 + qr + h * 8;   // = f (row bias!)
                float bv = bias[row];
                float v0 = fmaxf(acc[i][j][h * 2 + 0] + bv, 0.f);
                float v1 = fmaxf(acc[i][j][h * 2 + 1] + bv, 0.f);
                float2 pr = {v0, v1};
                *(float2*)(O + (long)row * Tn + col) = pr;
            }
        }
    }
}

// ---------------- fused bias: bc[m] = ib[m] + sum_j IW[m,j]*bq[j] ----------
__global__ __launch_bounds__(256)
void bias_comb_kernel(const float* __restrict__ IW, const float* __restrict__ bq,
                      const float* __restrict__ ib, float* __restrict__ bc) {
    int row  = blockIdx.x * 8 + (threadIdx.x >> 5);
    int lane = threadIdx.x & 31;
    float s = 0.f;
    for (int j = lane; j < Fn; j += 32) s += IW[(long)row * Fn + j] * bq[j];
    s = warpSum(s);
    if (lane == 0) bc[row] = s + ib[row];
}

// =============== TF32 mma flash attention ===================================
// 128 q-rows per CTA (8 warps x m16), 64-key tiles, dh = 128.
constexpr int FQ  = 128;
constexpr int FK  = 64;
constexpr int QLD = 132;   // bank = (4r + c) & 31 (132 % 32 == 4)
constexpr int VLD = 68;
constexpr int SLD = 68;
constexpr int NKT = (Sn + FK - 1) / FK;   // 36
constexpr int FLASH_SMEM = (FQ * QLD + 128 * VLD + FQ * SLD) * 4;   // 137216 B

__global__ __launch_bounds__(256)
void flash_mma_kernel(const float* __restrict__ Qg, const float* __restrict__ Kg,
                      const float* __restrict__ Vg, float* __restrict__ O) {
    extern __shared__ unsigned fsm[];
    unsigned* Qs  = fsm;                      // [FQ][QLD] tf32
    unsigned* KVs = Qs + FQ * QLD;            // K: [64][QLD] | V^T: [128][VLD]
    unsigned* Sc  = KVs + 128 * VLD;          // P: [FQ][SLD] tf32

    const int tid = threadIdx.x;
    const int w = tid >> 5, lane = tid & 31;
    const int qr = lane >> 2, qc = lane & 3;
    const int bh = blockIdx.y;
    const int b = bh / Hn, h = bh % Hn;
    const int q0 = blockIdx.x * FQ;
    const long base = (long)b * SF + (long)h * DH;
    const float scale = 0.08838834764831843f;   // 1/sqrt(128)

    // load Q tile (tf32)
    for (int i = tid; i < FQ * 32; i += 256) {
        int r = i >> 5, c4 = (i & 31) * 4;
        int s = q0 + r;
        float4 v = {0.f, 0.f, 0.f, 0.f};
        if (s < Sn) v = *(const float4*)(Qg + base + (long)s * Fn + c4);
        unsigned* p = &Qs[r * QLD + c4];
        p[0] = f2tf(v.x); p[1] = f2tf(v.y); p[2] = f2tf(v.z); p[3] = f2tf(v.w);
    }

    float mrow[2] = {-1e30f, -1e30f};
    float lrow[2] = {0.f, 0.f};
    float acc[16][4] = {};

    for (int kt = 0; kt < NKT; kt++) {
        const int k0 = kt * FK;
        // ---- K tile: KVs[key][d] ----
        for (int i = tid; i < FK * 32; i += 256) {
            int r = i >> 5, c4 = (i & 31) * 4;
            int s = k0 + r;
            float4 v = {0.f, 0.f, 0.f, 0.f};
            if (s < Sn) v = *(const float4*)(Kg + base + (long)s * Fn + c4);
            unsigned* p = &KVs[r * QLD + c4];
            p[0] = f2tf(v.x); p[1] = f2tf(v.y); p[2] = f2tf(v.z); p[3] = f2tf(v.w);
        }
        __syncthreads();   // Q (first iter) + K ready

        // ---- scores: S = Q K^T ----
        float sacc[8][4] = {};
        #pragma unroll
        for (int kk = 0; kk < 16; kk++) {
            int kks = kk * 8;
            unsigned a0 = Qs[(w * 16 + qr)     * QLD + kks + qc];
            unsigned a1 = Qs[(w * 16 + qr + 8) * QLD + kks + qc];
            unsigned a2 = Qs[(w * 16 + qr)     * QLD + kks + qc + 4];
            unsigned a3 = Qs[(w * 16 + qr + 8) * QLD + kks + qc + 4];
            #pragma unroll
            for (int j = 0; j < 8; j++) {
                unsigned b0 = KVs[(j * 8 + qr) * QLD + kks + qc];
                unsigned b1 = KVs[(j * 8 + qr) * QLD + kks + qc + 4];
                mma_tf32(sacc[j], a0, a1, a2, a3, b0, b1);
            }
        }
        __syncthreads();   // K consumed; KVs reusable for V

        // ---- V tile transposed: KVs[d][key] ----
        for (int i = tid; i < FK * 32; i += 256) {
            int r = i >> 5, c4 = (i & 31) * 4;
            int s = k0 + r;
            float4 v = {0.f, 0.f, 0.f, 0.f};
            if (s < Sn) v = *(const float4*)(Vg + base + (long)s * Fn + c4);
            KVs[(c4 + 0) * VLD + r] = f2tf(v.x);
            KVs[(c4 + 1) * VLD + r] = f2tf(v.y);
            KVs[(c4 + 2) * VLD + r] = f2tf(v.z);
            KVs[(c4 + 3) * VLD + r] = f2tf(v.w);
        }

        // ---- online softmax (registers + quad shuffles) ----
        float sv[8][4];
        float mx[2] = {-1e30f, -1e30f};
        #pragma unroll
        for (int j = 0; j < 8; j++)
            #pragma unroll
            for (int e = 0; e < 4; e++) {
                int lc = j * 8 + 2 * qc + (e & 1);
                float xv = sacc[j][e] * scale;
                xv = (k0 + lc < Sn) ? xv : -1e30f;
                sv[j][e] = xv;
                mx[e >> 1] = fmaxf(mx[e >> 1], xv);
            }
        #pragma unroll
        for (int i = 0; i < 2; i++) {
            mx[i] = fmaxf(mx[i], __shfl_xor_sync(0xFFFFFFFFu, mx[i], 1));
            mx[i] = fmaxf(mx[i], __shfl_xor_sync(0xFFFFFFFFu, mx[i], 2));
        }
        float corr[2], sum[2] = {0.f, 0.f};
        #pragma unroll
        for (int i = 0; i < 2; i++) {
            float mn = fmaxf(mrow[i], mx[i]);
            corr[i] = __expf(mrow[i] - mn);
            mrow[i] = mn;
        }
        #pragma unroll
        for (int j = 0; j < 8; j++)
            #pragma unroll
            for (int e = 0; e < 4; e++) {
                float p = __expf(sv[j][e] - mrow[e >> 1]);
                sum[e >> 1] += p;
                int lr = w * 16 + qr + ((e >> 1) << 3);
                Sc[lr * SLD + j * 8 + 2 * qc + (e & 1)] = f2tf(p);
            }
        #pragma unroll
        for (int i = 0; i < 2; i++) {
            sum[i] += __shfl_xor_sync(0xFFFFFFFFu, sum[i], 1);
            sum[i] += __shfl_xor_sync(0xFFFFFFFFu, sum[i], 2);
            lrow[i] = lrow[i] * corr[i] + sum[i];
        }
        // rescale accumulators
        #pragma unroll
        for (int j = 0; j < 16; j++) {
            acc[j][0] *= corr[0]; acc[j][1] *= corr[0];
            acc[j][2] *= corr[1]; acc[j][3] *= corr[1];
        }
        __syncthreads();   // V + P ready

        // ---- PV: acc += P V ----
        #pragma unroll
        for (int kk = 0; kk < 8; kk++) {
            int kks = kk * 8;
            unsigned a0 = Sc[(w * 16 + qr)     * SLD + kks + qc];
            unsigned a1 = Sc[(w * 16 + qr + 8) * SLD + kks + qc];
            unsigned a2 = Sc[(w * 16 + qr)     * SLD + kks + qc + 4];
            unsigned a3 = Sc[(w * 16 + qr + 8) * SLD + kks + qc + 4];
            #pragma unroll
            for (int j = 0; j < 16; j++) {
                unsigned b0 = KVs[(j * 8 + qr) * VLD + kks + qc];
                unsigned b1 = KVs[(j * 8 + qr) * VLD + kks + qc + 4];
                mma_tf32(acc[j], a0, a1, a2, a3, b0, b1);
            }
        }
        __syncthreads();   // PV done before next K overwrites KVs
    }

    // ---- write O ----
    float inv0 = 1.f / lrow[0], inv1 = 1.f / lrow[1];
    int s1 = q0 + w * 16 + qr, s2 = s1 + 8;
    #pragma unroll
    for (int j = 0; j < 16; j++) {
        int d = j * 8 + 2 * qc;
        if (s1 < Sn) {
            float2 pr = {acc[j][0] * inv0, acc[j][1] * inv0};
            *(float2*)(O + base + (long)s1 * Fn + d) = pr;
        }
        if (s2 < Sn) {
            float2 pr = {acc[j][2] * inv1, acc[j][3] * inv1};
            *(float2*)(O + base + (long)s2 * Fn + d) = pr;
        }
    }
}

// ---------------- fused residual add + LayerNorm (F = 1024 = 256*4) ---------
__global__ __launch_bounds__(256)
void add_ln_kernel(float* __restrict__ src, const float* __restrict__ res,
                   const float* __restrict__ g, const float* __restrict__ bta) {
    long row = blockIdx.x;
    float* p = src + row * (long)Fn;
    const float* q = res + row * (long)Fn;
    int tid = threadIdx.x;
    int w = tid >> 5, lane = tid & 31;

    float v[4];
    float s = 0.f, s2 = 0.f;
    #pragma unroll
    for (int i = 0; i < 4; i++) {
        int f = tid + i * 256;
        float t = p[f] + q[f];
        v[i] = t;
        s += t;
        s2 += t * t;
    }
    __shared__ float sh0[8], sh1[8], bmean, brstd;
    s = warpSum(s); s2 = warpSum(s2);
    if (lane == 0) { sh0[w] = s; sh1[w] = s2; }
    __syncthreads();
    if (w == 0) {
        float a  = lane < 8 ? sh0[lane] : 0.f;
        float b2 = lane < 8 ? sh1[lane] : 0.f;
        a = warpSum(a); b2 = warpSum(b2);
        if (lane == 0) {
            float mean = a * (1.f / Fn);
            float var  = b2 * (1.f / Fn) - mean * mean;
            bmean = mean;
            brstd = rsqrtf(var + 1e-5f);
        }
    }
    __syncthreads();
    float mean = bmean, rstd = brstd;
    #pragma unroll
    for (int i = 0; i < 4; i++) {
        int f = tid + i * 256;
        p[f] = (v[i] - mean) * rstd * g[f] + bta[f];
    }
}

// ---------------- host driver ----------------
static inline int cdiv(int a, int b) { return (a + b - 1) / b; }

extern "C" void kernel_launch(void* const* d_in, const int* in_sizes, int n_in,
                              void* d_out, int out_size) {
    const float* x     = (const float*)d_in[0];
    const float* proto = (const float*)d_in[1];
    const float* wq    = (const float*)d_in[2];
    const float* bq    = (const float*)d_in[3];
    const float* wk    = (const float*)d_in[4];
    const float* bk    = (const float*)d_in[5];
    const float* in_w  = (const float*)d_in[6];
    const float* in_b  = (const float*)d_in[7];
    const float* out_w = (const float*)d_in[8];
    const float* out_b = (const float*)d_in[9];
    const float* l1_w  = (const float*)d_in[10];
    const float* l1_b  = (const float*)d_in[11];
    const float* l2_w  = (const float*)d_in[12];
    const float* l2_b  = (const float*)d_in[13];
    const float* ln1_g = (const float*)d_in[14];
    const float* ln1_b = (const float*)d_in[15];
    const float* ln2_g = (const float*)d_in[16];
    const float* ln2_b = (const float*)d_in[17];
    const float* emb_w = (const float*)d_in[18];
    const float* emb_b = (const float*)d_in[19];
    float* out = (float*)d_out;

    float *src, *Q, *K, *V, *ao, *tp, *ff, *wc, *bc;
    cudaGetSymbolAddress((void**)&src, g_src);
    cudaGetSymbolAddress((void**)&Q,   g_Q);
    cudaGetSymbolAddress((void**)&K,   g_K);
    cudaGetSymbolAddress((void**)&V,   g_V);
    cudaGetSymbolAddress((void**)&ao,  g_ao);
    cudaGetSymbolAddress((void**)&tp,  g_t);
    cudaGetSymbolAddress((void**)&ff,  g_ff);
    cudaGetSymbolAddress((void**)&wc,  g_wc);
    cudaGetSymbolAddress((void**)&bc,  g_bc);

    static bool attr_done = false;
    if (!attr_done) {
        cudaFuncSetAttribute(flash_mma_kernel,
                             cudaFuncAttributeMaxDynamicSharedMemorySize,
                             FLASH_SMEM);
        attr_done = true;
    }

    const int BS = Bn * Sn;                       // 8992 rows
    const long FF = (long)Fn * Fn;
    const int MY = cdiv(BS, 128);                 // 71 row-blocks

    // 0) build src
    {
        long total = (long)Bn * Sn * Fn;
        build_src_kernel<<<(unsigned)((total + 255) / 256), 256>>>(x, proto, src);
    }

    // 1) fuse q/k convs into in-projections: Wc = IW_{q|k} @ W_{q|k}
    for (int l = 0; l < Ln; l++) {
        const float* IW  = in_w + (long)l * 3 * FF;
        const float* IB  = in_b + (long)l * 3 * Fn;
        dim3 g(8, 8);
        gemm_mma_kernel<false, 0><<<g, 256>>>(IW, wq + (long)l * FF, nullptr,
                                              wc + (long)(2 * l) * FF,
                                              Fn, Fn, Fn, Fn, Fn, Fn);
        gemm_mma_kernel<false, 0><<<g, 256>>>(IW + FF, wk + (long)l * FF, nullptr,
                                              wc + (long)(2 * l + 1) * FF,
                                              Fn, Fn, Fn, Fn, Fn, Fn);
        bias_comb_kernel<<<Fn / 8, 256>>>(IW, bq + (long)l * Fn, IB,
                                          bc + (long)(2 * l) * Fn);
        bias_comb_kernel<<<Fn / 8, 256>>>(IW + FF, bk + (long)l * Fn, IB + Fn,
                                          bc + (long)(2 * l + 1) * Fn);
    }

    for (int l = 0; l < Ln; l++) {
        const float* IW  = in_w + (long)l * 3 * FF;
        const float* IB  = in_b + (long)l * 3 * Fn;
        const float* OW  = out_w + (long)l * FF;
        const float* OB  = out_b + (long)l * Fn;
        const float* W1  = l1_w + (long)l * DFFn * Fn;
        const float* B1  = l1_b + (long)l * DFFn;
        const float* W2  = l2_w + (long)l * Fn * DFFn;
        const float* B2  = l2_b + (long)l * Fn;

        dim3 gFF(8, MY);

        // Q = src @ WcQ^T + bcQ  (fused conv_q + in-proj-q)
        gemm_mma_kernel<true, 0><<<gFF, 256>>>(src, wc + (long)(2 * l) * FF,
                                               bc + (long)(2 * l) * Fn, Q,
                                               BS, Fn, Fn, Fn, Fn, Fn);
        // K = src @ WcK^T + bcK
        gemm_mma_kernel<true, 0><<<gFF, 256>>>(src, wc + (long)(2 * l + 1) * FF,
                                               bc + (long)(2 * l + 1) * Fn, K,
                                               BS, Fn, Fn, Fn, Fn, Fn);
        // V = src @ IW_v^T + ib_v
        gemm_mma_kernel<true, 0><<<gFF, 256>>>(src, IW + 2 * FF, IB + 2 * Fn, V,
                                               BS, Fn, Fn, Fn, Fn, Fn);

        // flash attention -> ao
        {
            dim3 g(cdiv(Sn, FQ), Bn * Hn);
            flash_mma_kernel<<<g, 256, FLASH_SMEM>>>(Q, K, V, ao);
        }

        // out-proj: tp = ao @ OW^T + OB
        gemm_mma_kernel<true, 0><<<gFF, 256>>>(ao, OW, OB, tp, BS, Fn, Fn,
                                               Fn, Fn, Fn);
        // src = LN(src + tp)
        add_ln_kernel<<<BS, 256>>>(src, tp, ln1_g + (long)l * Fn, ln1_b + (long)l * Fn);

        // ffn1: ff = relu(src @ W1^T + B1)
        {
            dim3 g(1, MY);
            gemm_mma_kernel<true, 1><<<g, 256>>>(src, W1, B1, ff, BS, DFFn, Fn,
                                                 Fn, Fn, DFFn);
        }
        // ffn2: tp = ff @ W2^T + B2
        gemm_mma_kernel<true, 0><<<gFF, 256>>>(ff, W2, B2, tp, BS, Fn, DFFn,
                                               DFFn, DFFn, Fn);
        // src = LN(src + tp)
        add_ln_kernel<<<BS, 256>>>(src, tp, ln2_g + (long)l * Fn, ln2_b + (long)l * Fn);
    }

    // conv head -> out (B, F, T), ReLU
    {
        dim3 g(Tn / 128, Fn / 128, Bn);
        conv_mma_kernel<<<g, 256>>>(src, emb_w, emb_b, out);
    }
    (void)in_sizes; (void)n_in; (void)out_size;
}

// round 4
// speedup vs baseline: 4.1867x; 1.2734x over previous
#include <cuda_runtime.h>
#include <math.h>

// ---------------- problem constants ----------------
constexpr int Bn   = 4;
constexpr int Tn   = 2048;
constexpr int Fn   = 1024;
constexpr int Cn   = 200;
constexpr int Hn   = 8;
constexpr int DFFn = 128;
constexpr int Ln   = 2;
constexpr int Sn   = Tn + Cn;         // 2248
constexpr int DH   = Fn / Hn;         // 128
constexpr int F3   = 3 * Fn;          // 3072

constexpr long SF  = (long)Sn * Fn;
constexpr long SF3 = (long)Sn * F3;

// ---------------- scratch (device globals) ----------------
__device__ float g_src[(long)Bn * Sn * Fn];
__device__ float g_qkv[(long)Bn * Sn * F3];
__device__ float g_ao [(long)Bn * Sn * Fn];
__device__ float g_t  [(long)Bn * Sn * Fn];
__device__ float g_ff [(long)Bn * Sn * DFFn];
__device__ float g_wc3[(long)Ln * F3 * Fn];   // fused [WcQ;WcK;IWv] per layer
__device__ float g_bc3[(long)Ln * F3];
__device__ float g_wr [(long)Fn * F3];        // tap-major conv weights

// ---------------- helpers ----------------
__inline__ __device__ float warpSum(float v) {
    #pragma unroll
    for (int o = 16; o; o >>= 1) v += __shfl_xor_sync(0xFFFFFFFFu, v, o);
    return v;
}
__device__ __forceinline__ unsigned f2tf(float f) {
    unsigned u;
    asm("cvt.rna.tf32.f32 %0, %1;" : "=r"(u) : "f"(f));
    return u;
}
__device__ __forceinline__ void mma_tf32(float c[4],
        unsigned a0, unsigned a1, unsigned a2, unsigned a3,
        unsigned b0, unsigned b1) {
    asm volatile(
        "mma.sync.aligned.m16n8k8.row.col.f32.tf32.tf32.f32 "
        "{%0,%1,%2,%3}, {%4,%5,%6,%7}, {%8,%9}, {%0,%1,%2,%3};"
        : "+f"(c[0]), "+f"(c[1]), "+f"(c[2]), "+f"(c[3])
        : "r"(a0), "r"(a1), "r"(a2), "r"(a3), "r"(b0), "r"(b1));
}
__device__ __forceinline__ void cpa(unsigned saddr, const float* g, bool pred) {
    int sz = pred ? 16 : 0;
    asm volatile("cp.async.cg.shared.global [%0], [%1], 16, %2;"
                 :: "r"(saddr), "l"(g), "r"(sz));
}
#define CP_COMMIT() asm volatile("cp.async.commit_group;")

// ---------------- build src ----------------
__global__ void build_src_kernel(const float* __restrict__ x,
                                 const float* __restrict__ proto,
                                 float* __restrict__ src) {
    long i = (long)blockIdx.x * 256 + threadIdx.x;
    const long total = (long)Bn * Sn * Fn;
    if (i >= total) return;
    int f  = (int)(i % Fn);
    long bs = i / Fn;
    int s  = (int)(bs % Sn);
    int b  = (int)(bs / Sn);
    float v;
    if (s < Tn)  v = x[((long)b * Tn + s) * Fn + f];
    else         v = proto[(long)f * Cn + (s - Tn)];
    src[i] = v;
}

// ---------------- conv weight reorder: W[f][fi*3+tap] -> Wr[f][tap*F+fi] ----
__global__ void reorder_conv_w(const float* __restrict__ W, float* __restrict__ Wr) {
    long i = (long)blockIdx.x * 256 + threadIdx.x;
    if (i >= (long)Fn * F3) return;
    int f = (int)(i / F3);
    int k = (int)(i % F3);
    int tap = k / Fn, fi = k % Fn;
    Wr[i] = W[(long)f * F3 + fi * 3 + tap];
}

// ---------------- fused bias: bc[m] = ib[m] + sum_j IW[m,j]*bq[j] ----------
__global__ __launch_bounds__(256)
void bias_comb_kernel(const float* __restrict__ IW, const float* __restrict__ bq,
                      const float* __restrict__ ib, float* __restrict__ bc) {
    int row  = blockIdx.x * 8 + (threadIdx.x >> 5);
    int lane = threadIdx.x & 31;
    float s = 0.f;
    for (int j = lane; j < Fn; j += 32) s += IW[(long)row * Fn + j] * bq[j];
    s = warpSum(s);
    if (lane == 0) bc[row] = s + ib[row];
}

// =============== non-pipelined GEMM for weight-combine (B = (K,N) row-major) =
constexpr int GLD = 36;   // smem word stride; bank = (4r + c) & 31

__global__ __launch_bounds__(256)
void gemm_nt_kernel(const float* __restrict__ A, const float* __restrict__ Bm,
                    float* __restrict__ C, int M, int N, int K,
                    int lda, int ldb, int ldc) {
    __shared__ unsigned As[128 * GLD];
    __shared__ unsigned Bs[128 * GLD];
    const int tid = threadIdx.x;
    const int w = tid >> 5, lane = tid & 31;
    const int qr = lane >> 2, qc = lane & 3;
    const int wm = (w & 3) * 32, wn = (w >> 2) * 64;
    const int m0 = blockIdx.y * 128, n0 = blockIdx.x * 128;

    float acc[2][8][4] = {};
    for (int k0 = 0; k0 < K; k0 += 32) {
        {
            int c = (tid & 7) * 4;
            #pragma unroll
            for (int r = tid >> 3; r < 128; r += 32) {
                float4 v = *(const float4*)(A + (long)(m0 + r) * lda + k0 + c);
                unsigned* p = &As[r * GLD + c];
                p[0] = f2tf(v.x); p[1] = f2tf(v.y);
                p[2] = f2tf(v.z); p[3] = f2tf(v.w);
            }
        }
        for (int i = tid; i < 128 * 32; i += 256) {
            int k = i >> 7, n = i & 127;
            Bs[n * GLD + k] = f2tf(Bm[(long)(k0 + k) * ldb + n0 + n]);
        }
        __syncthreads();
        #pragma unroll
        for (int kk = 0; kk < 32; kk += 8) {
            unsigned af[2][4], bf[8][2];
            #pragma unroll
            for (int i = 0; i < 2; i++) {
                int r = wm + i * 16;
                af[i][0] = As[(r + qr)     * GLD + kk + qc];
                af[i][1] = As[(r + qr + 8) * GLD + kk + qc];
                af[i][2] = As[(r + qr)     * GLD + kk + qc + 4];
                af[i][3] = As[(r + qr + 8) * GLD + kk + qc + 4];
            }
            #pragma unroll
            for (int j = 0; j < 8; j++) {
                bf[j][0] = Bs[(wn + j * 8 + qr) * GLD + kk + qc];
                bf[j][1] = Bs[(wn + j * 8 + qr) * GLD + kk + qc + 4];
            }
            #pragma unroll
            for (int i = 0; i < 2; i++)
                #pragma unroll
                for (int j = 0; j < 8; j++)
                    mma_tf32(acc[i][j], af[i][0], af[i][1], af[i][2], af[i][3],
                             bf[j][0], bf[j][1]);
        }
        __syncthreads();
    }
    #pragma unroll
    for (int i = 0; i < 2; i++)
        #pragma unroll
        for (int j = 0; j < 8; j++) {
            int col = n0 + wn + j * 8 + 2 * qc;
            #pragma unroll
            for (int h = 0; h < 2; h++) {
                int row = m0 + wm + i * 16 + qr + h * 8;
                float2 pr = {acc[i][j][h * 2 + 0], acc[i][j][h * 2 + 1]};
                *(float2*)(C + (long)row * ldc + col) = pr;
            }
        }
}

// =============== pipelined TF32 GEMM (B = (N,K) row-major weights) ===========
constexpr int GEMM_SMEM = 4 * (4 * 128 * GLD);   // 73728 B

template<int ACT>
__global__ __launch_bounds__(256)
void gemm_tb_async(const float* __restrict__ A, const float* __restrict__ Bw,
                   const float* __restrict__ bias, float* __restrict__ C,
                   int M, int N, int K, int lda, int ldb, int ldc) {
    extern __shared__ float gsm[];
    float* As = gsm;
    float* Bs = gsm + 2 * 128 * GLD;

    const int tid = threadIdx.x;
    const int w = tid >> 5, lane = tid & 31;
    const int qr = lane >> 2, qc = lane & 3;
    const int wm = (w & 3) * 32, wn = (w >> 2) * 64;
    const int m0 = blockIdx.y * 128, n0 = blockIdx.x * 128;
    const int cc = (tid & 7) * 4, rr = tid >> 3;

    float acc[2][8][4] = {};
    const int nK = K >> 5;

    // prefetch stage 0
    {
        #pragma unroll
        for (int r = rr; r < 128; r += 32) {
            int gm = m0 + r; bool p = gm < M;
            cpa((unsigned)__cvta_generic_to_shared(As + r * GLD + cc),
                A + (long)(p ? gm : 0) * lda + cc, p);
        }
        #pragma unroll
        for (int r = rr; r < 128; r += 32) {
            int gn = n0 + r; bool p = gn < N;
            cpa((unsigned)__cvta_generic_to_shared(Bs + r * GLD + cc),
                Bw + (long)(p ? gn : 0) * ldb + cc, p);
        }
        CP_COMMIT();
    }

    for (int kt = 0; kt < nK; kt++) {
        if (kt + 1 < nK) {
            int k0 = (kt + 1) << 5;
            int st = (kt + 1) & 1;
            float* Ad = As + st * 128 * GLD;
            float* Bd = Bs + st * 128 * GLD;
            #pragma unroll
            for (int r = rr; r < 128; r += 32) {
                int gm = m0 + r; bool p = gm < M;
                cpa((unsigned)__cvta_generic_to_shared(Ad + r * GLD + cc),
                    A + (long)(p ? gm : 0) * lda + k0 + cc, p);
            }
            #pragma unroll
            for (int r = rr; r < 128; r += 32) {
                int gn = n0 + r; bool p = gn < N;
                cpa((unsigned)__cvta_generic_to_shared(Bd + r * GLD + cc),
                    Bw + (long)(p ? gn : 0) * ldb + k0 + cc, p);
            }
            CP_COMMIT();
            asm volatile("cp.async.wait_group 1;");
        } else {
            asm volatile("cp.async.wait_group 0;");
        }
        __syncthreads();
        const float* Ac = As + (kt & 1) * 128 * GLD;
        const float* Bc = Bs + (kt & 1) * 128 * GLD;
        #pragma unroll
        for (int kk = 0; kk < 32; kk += 8) {
            unsigned af[2][4], bf[8][2];
            #pragma unroll
            for (int i = 0; i < 2; i++) {
                int r = wm + i * 16;
                af[i][0] = f2tf(Ac[(r + qr)     * GLD + kk + qc]);
                af[i][1] = f2tf(Ac[(r + qr + 8) * GLD + kk + qc]);
                af[i][2] = f2tf(Ac[(r + qr)     * GLD + kk + qc + 4]);
                af[i][3] = f2tf(Ac[(r + qr + 8) * GLD + kk + qc + 4]);
            }
            #pragma unroll
            for (int j = 0; j < 8; j++) {
                bf[j][0] = f2tf(Bc[(wn + j * 8 + qr) * GLD + kk + qc]);
                bf[j][1] = f2tf(Bc[(wn + j * 8 + qr) * GLD + kk + qc + 4]);
            }
            #pragma unroll
            for (int i = 0; i < 2; i++)
                #pragma unroll
                for (int j = 0; j < 8; j++)
                    mma_tf32(acc[i][j], af[i][0], af[i][1], af[i][2], af[i][3],
                             bf[j][0], bf[j][1]);
        }
        __syncthreads();
    }
    #pragma unroll
    for (int i = 0; i < 2; i++)
        #pragma unroll
        for (int j = 0; j < 8; j++) {
            int col = n0 + wn + j * 8 + 2 * qc;
            float b0 = bias ? bias[col]     : 0.f;
            float b1 = bias ? bias[col + 1] : 0.f;
            #pragma unroll
            for (int h = 0; h < 2; h++) {
                int row = m0 + wm + i * 16 + qr + h * 8;
                if (row >= M) continue;
                float v0 = acc[i][j][h * 2 + 0] + b0;
                float v1 = acc[i][j][h * 2 + 1] + b1;
                if (ACT == 1) { v0 = fmaxf(v0, 0.f); v1 = fmaxf(v1, 0.f); }
                float2 pr = {v0, v1};
                *(float2*)(C + (long)row * ldc + col) = pr;
            }
        }
}

// =============== pipelined conv head (tap-major K) ==========================
__global__ __launch_bounds__(256)
void conv_mma_async(const float* __restrict__ src, const float* __restrict__ Wr,
                    const float* __restrict__ bias, float* __restrict__ out) {
    extern __shared__ float gsm[];
    float* As = gsm;
    float* Bs = gsm + 2 * 128 * GLD;

    const int b = blockIdx.z;
    const float* Sp = src + (long)b * SF;
    float* O = out + (long)b * Fn * Tn;

    const int tid = threadIdx.x;
    const int w = tid >> 5, lane = tid & 31;
    const int qr = lane >> 2, qc = lane & 3;
    const int wm = (w & 3) * 32, wn = (w >> 2) * 64;
    const int m0 = blockIdx.y * 128;     // f
    const int n0 = blockIdx.x * 128;     // t
    const int cc = (tid & 7) * 4, rr = tid >> 3;
    const int nK = F3 >> 5;              // 96

    float acc[2][8][4] = {};

    auto prefetch = [&](int k0, int st) {
        float* Ad = As + st * 128 * GLD;
        float* Bd = Bs + st * 128 * GLD;
        #pragma unroll
        for (int r = rr; r < 128; r += 32)
            cpa((unsigned)__cvta_generic_to_shared(Ad + r * GLD + cc),
                Wr + (long)(m0 + r) * F3 + k0 + cc, true);
        int tap = k0 >> 10;                 // k0 / Fn
        int fi  = (k0 & 1023) + cc;
        #pragma unroll
        for (int r = rr; r < 128; r += 32) {
            int t = n0 + r + tap - 1;
            bool p = (t >= 0 && t < Tn);
            cpa((unsigned)__cvta_generic_to_shared(Bd + r * GLD + cc),
                Sp + (long)(p ? t : 0) * Fn + fi, p);
        }
        CP_COMMIT();
    };

    prefetch(0, 0);
    for (int kt = 0; kt < nK; kt++) {
        if (kt + 1 < nK) {
            prefetch((kt + 1) << 5, (kt + 1) & 1);
            asm volatile("cp.async.wait_group 1;");
        } else {
            asm volatile("cp.async.wait_group 0;");
        }
        __syncthreads();
        const float* Ac = As + (kt & 1) * 128 * GLD;
        const float* Bc = Bs + (kt & 1) * 128 * GLD;
        #pragma unroll
        for (int kk = 0; kk < 32; kk += 8) {
            unsigned af[2][4], bf[8][2];
            #pragma unroll
            for (int i = 0; i < 2; i++) {
                int r = wm + i * 16;
                af[i][0] = f2tf(Ac[(r + qr)     * GLD + kk + qc]);
                af[i][1] = f2tf(Ac[(r + qr + 8) * GLD + kk + qc]);
                af[i][2] = f2tf(Ac[(r + qr)     * GLD + kk + qc + 4]);
                af[i][3] = f2tf(Ac[(r + qr + 8) * GLD + kk + qc + 4]);
            }
            #pragma unroll
            for (int j = 0; j < 8; j++) {
                bf[j][0] = f2tf(Bc[(wn + j * 8 + qr) * GLD + kk + qc]);
                bf[j][1] = f2tf(Bc[(wn + j * 8 + qr) * GLD + kk + qc + 4]);
            }
            #pragma unroll
            for (int i = 0; i < 2; i++)
                #pragma unroll
                for (int j = 0; j < 8; j++)
                    mma_tf32(acc[i][j], af[i][0], af[i][1], af[i][2], af[i][3],
                             bf[j][0], bf[j][1]);
        }
        __syncthreads();
    }
    #pragma unroll
    for (int i = 0; i < 2; i++)
        #pragma unroll
        for (int j = 0; j < 8; j++) {
            int col = n0 + wn + j * 8 + 2 * qc;
            #pragma unroll
            for (int h = 0; h < 2; h++) {
                int row = m0 + wm + i * 16 + qr + h * 8;   // f
                float bv = bias[row];
                float v0 = fmaxf(acc[i][j][h * 2 + 0] + bv, 0.f);
                float v1 = fmaxf(acc[i][j][h * 2 + 1] + bv, 0.f);
                float2 pr = {v0, v1};
                *(float2*)(O + (long)row * Tn + col) = pr;
            }
        }
}

// =============== pipelined TF32 flash attention =============================
constexpr int QLD = 132, KLD = 132, VLD = 68, SLD = 68, VSTLD = 132;
constexpr int NKT = (Sn + 63) / 64;            // 36
constexpr int OFF_Q = 0;
constexpr int OFF_K = 128 * QLD;               // 16896
constexpr int OFF_V = OFF_K + 2 * 64 * KLD;    // 33792
constexpr int OFF_S = OFF_V + 128 * VLD;       // 42496
constexpr int FLASH_SMEM = (OFF_S + 128 * SLD) * 4;   // 204800 B

__global__ __launch_bounds__(256)
void flash_mma_kernel(const float* __restrict__ QKV, float* __restrict__ O) {
    extern __shared__ float fsm[];
    float* Qs  = fsm + OFF_Q;
    float* Ks  = fsm + OFF_K;
    float* Vt  = fsm + OFF_V;
    float* Sc  = fsm + OFF_S;      // aliases V staging
    float* Vst = Sc;

    const int tid = threadIdx.x;
    const int w = tid >> 5, lane = tid & 31;
    const int qr = lane >> 2, qc = lane & 3;
    const int bh = blockIdx.y;
    const int b = bh / Hn, h = bh % Hn;
    const int q0 = blockIdx.x * 128;
    const float scale = 0.08838834764831843f;

    const float* Qg = QKV + (long)b * SF3 + h * DH;
    const float* Kg = Qg + Fn;
    const float* Vg = Qg + 2 * Fn;

    const int cL = (tid & 31) * 4;
    const int rW = tid >> 5;

    // Q cp.async (group 0)
    #pragma unroll
    for (int r = rW; r < 128; r += 8) {
        int s = q0 + r; bool p = s < Sn;
        cpa((unsigned)__cvta_generic_to_shared(Qs + r * QLD + cL),
            Qg + (long)(p ? s : 0) * F3 + cL, p);
    }
    CP_COMMIT();
    // K0 (group 1)
    #pragma unroll
    for (int r = rW; r < 64; r += 8) {
        int s = r; bool p = s < Sn;
        cpa((unsigned)__cvta_generic_to_shared(Ks + r * KLD + cL),
            Kg + (long)s * F3 + cL, p);
    }
    CP_COMMIT();

    asm volatile("cp.async.wait_group 1;");
    __syncthreads();
    // in-place Q -> tf32
    for (int i = tid; i < 128 * 32; i += 256) {
        int r = i >> 5, c4 = (i & 31) * 4;
        float4* p = (float4*)(Qs + r * QLD + c4);
        float4 v = *p;
        v.x = __uint_as_float(f2tf(v.x)); v.y = __uint_as_float(f2tf(v.y));
        v.z = __uint_as_float(f2tf(v.z)); v.w = __uint_as_float(f2tf(v.w));
        *p = v;
    }

    float mrow[2] = {-1e30f, -1e30f};
    float lrow[2] = {0.f, 0.f};
    float acc[16][4] = {};

    for (int kt = 0; kt < NKT; kt++) {
        const int k0 = kt * 64;
        // prefetch V_kt into staging (alias Sc — safe: prev PV done at loop-end sync)
        #pragma unroll
        for (int r = rW; r < 64; r += 8) {
            int s = k0 + r; bool p = s < Sn;
            cpa((unsigned)__cvta_generic_to_shared(Vst + r * VSTLD + cL),
                Vg + (long)(p ? s : 0) * F3 + cL, p);
        }
        CP_COMMIT();
        bool more = (kt + 1 < NKT);
        if (more) {
            float* Kd = Ks + ((kt + 1) & 1) * 64 * KLD;
            #pragma unroll
            for (int r = rW; r < 64; r += 8) {
                int s = k0 + 64 + r; bool p = s < Sn;
                cpa((unsigned)__cvta_generic_to_shared(Kd + r * KLD + cL),
                    Kg + (long)(p ? s : 0) * F3 + cL, p);
            }
            CP_COMMIT();
            asm volatile("cp.async.wait_group 2;");
        } else {
            asm volatile("cp.async.wait_group 1;");
        }
        __syncthreads();                       // K_kt visible (and Q cvt, iter 0)

        float* Kc = Ks + (kt & 1) * 64 * KLD;
        // in-place K -> tf32
        for (int i = tid; i < 64 * 32; i += 256) {
            int r = i >> 5, c4 = (i & 31) * 4;
            float4* p = (float4*)(Kc + r * KLD + c4);
            float4 v = *p;
            v.x = __uint_as_float(f2tf(v.x)); v.y = __uint_as_float(f2tf(v.y));
            v.z = __uint_as_float(f2tf(v.z)); v.w = __uint_as_float(f2tf(v.w));
            *p = v;
        }
        __syncthreads();

        // ---- QK^T ----
        float sacc[8][4] = {};
        #pragma unroll
        for (int kk = 0; kk < 16; kk++) {
            int kks = kk * 8;
            unsigned a0 = __float_as_uint(Qs[(w * 16 + qr)     * QLD + kks + qc]);
            unsigned a1 = __float_as_uint(Qs[(w * 16 + qr + 8) * QLD + kks + qc]);
            unsigned a2 = __float_as_uint(Qs[(w * 16 + qr)     * QLD + kks + qc + 4]);
            unsigned a3 = __float_as_uint(Qs[(w * 16 + qr + 8) * QLD + kks + qc + 4]);
            #pragma unroll
            for (int j = 0; j < 8; j++) {
                unsigned b0 = __float_as_uint(Kc[(j * 8 + qr) * KLD + kks + qc]);
                unsigned b1 = __float_as_uint(Kc[(j * 8 + qr) * KLD + kks + qc + 4]);
                mma_tf32(sacc[j], a0, a1, a2, a3, b0, b1);
            }
        }
        if (more) asm volatile("cp.async.wait_group 1;");
        else      asm volatile("cp.async.wait_group 0;");
        __syncthreads();                       // V staging visible

        // ---- transpose + cvt V: warp w owns d rows [w*16, w*16+16) ----
        #pragma unroll
        for (int dd = 0; dd < 16; dd++) {
            int d = w * 16 + dd;
            float v0 = Vst[lane        * VSTLD + d];
            float v1 = Vst[(lane + 32) * VSTLD + d];
            Vt[d * VLD + lane]      = __uint_as_float(f2tf(v0));
            Vt[d * VLD + lane + 32] = __uint_as_float(f2tf(v1));
        }
        __syncthreads();                       // transpose done before Sc writes

        // ---- online softmax ----
        float sv[8][4];
        float mx[2] = {-1e30f, -1e30f};
        #pragma unroll
        for (int j = 0; j < 8; j++)
            #pragma unroll
            for (int e = 0; e < 4; e++) {
                int lc = j * 8 + 2 * qc + (e & 1);
                float xv = sacc[j][e] * scale;
                xv = (k0 + lc < Sn) ? xv : -1e30f;
                sv[j][e] = xv;
                mx[e >> 1] = fmaxf(mx[e >> 1], xv);
            }
        #pragma unroll
        for (int i = 0; i < 2; i++) {
            mx[i] = fmaxf(mx[i], __shfl_xor_sync(0xFFFFFFFFu, mx[i], 1));
            mx[i] = fmaxf(mx[i], __shfl_xor_sync(0xFFFFFFFFu, mx[i], 2));
        }
        float corr[2], sum[2] = {0.f, 0.f};
        #pragma unroll
        for (int i = 0; i < 2; i++) {
            float mn = fmaxf(mrow[i], mx[i]);
            corr[i] = __expf(mrow[i] - mn);
            mrow[i] = mn;
        }
        #pragma unroll
        for (int j = 0; j < 8; j++)
            #pragma unroll
            for (int e = 0; e < 4; e++) {
                float p = __expf(sv[j][e] - mrow[e >> 1]);
                sum[e >> 1] += p;
                int lr = w * 16 + qr + ((e >> 1) << 3);
                Sc[lr * SLD + j * 8 + 2 * qc + (e & 1)] = __uint_as_float(f2tf(p));
            }
        #pragma unroll
        for (int i = 0; i < 2; i++) {
            sum[i] += __shfl_xor_sync(0xFFFFFFFFu, sum[i], 1);
            sum[i] += __shfl_xor_sync(0xFFFFFFFFu, sum[i], 2);
            lrow[i] = lrow[i] * corr[i] + sum[i];
        }
        #pragma unroll
        for (int j = 0; j < 16; j++) {
            acc[j][0] *= corr[0]; acc[j][1] *= corr[0];
            acc[j][2] *= corr[1]; acc[j][3] *= corr[1];
        }
        __syncwarp();                          // Sc is warp-private; warp fence

        // ---- PV ----
        #pragma unroll
        for (int kk = 0; kk < 8; kk++) {
            int kks = kk * 8;
            unsigned a0 = __float_as_uint(Sc[(w * 16 + qr)     * SLD + kks + qc]);
            unsigned a1 = __float_as_uint(Sc[(w * 16 + qr + 8) * SLD + kks + qc]);
            unsigned a2 = __float_as_uint(Sc[(w * 16 + qr)     * SLD + kks + qc + 4]);
            unsigned a3 = __float_as_uint(Sc[(w * 16 + qr + 8) * SLD + kks + qc + 4]);
            #pragma unroll
            for (int j = 0; j < 16; j++) {
                unsigned b0 = __float_as_uint(Vt[(j * 8 + qr) * VLD + kks + qc]);
                unsigned b1 = __float_as_uint(Vt[(j * 8 + qr) * VLD + kks + qc + 4]);
                mma_tf32(acc[j], a0, a1, a2, a3, b0, b1);
            }
        }
        __syncthreads();                       // PV done: Vst/Sc/Vt reusable
    }

    // ---- write O into ao[BS][Fn] ----
    const long obase = (long)b * SF + (long)h * DH;
    float inv0 = 1.f / lrow[0], inv1 = 1.f / lrow[1];
    int s1 = q0 + w * 16 + qr, s2 = s1 + 8;
    #pragma unroll
    for (int j = 0; j < 16; j++) {
        int d = j * 8 + 2 * qc;
        if (s1 < Sn) {
            float2 pr = {acc[j][0] * inv0, acc[j][1] * inv0};
            *(float2*)(O + obase + (long)s1 * Fn + d) = pr;
        }
        if (s2 < Sn) {
            float2 pr = {acc[j][2] * inv1, acc[j][3] * inv1};
            *(float2*)(O + obase + (long)s2 * Fn + d) = pr;
        }
    }
}

// ---------------- fused residual add + LayerNorm ----------------
__global__ __launch_bounds__(256)
void add_ln_kernel(float* __restrict__ src, const float* __restrict__ res,
                   const float* __restrict__ g, const float* __restrict__ bta) {
    long row = blockIdx.x;
    float* p = src + row * (long)Fn;
    const float* q = res + row * (long)Fn;
    int tid = threadIdx.x;
    int w = tid >> 5, lane = tid & 31;

    float v[4];
    float s = 0.f, s2 = 0.f;
    #pragma unroll
    for (int i = 0; i < 4; i++) {
        int f = tid + i * 256;
        float t = p[f] + q[f];
        v[i] = t;
        s += t;
        s2 += t * t;
    }
    __shared__ float sh0[8], sh1[8], bmean, brstd;
    s = warpSum(s); s2 = warpSum(s2);
    if (lane == 0) { sh0[w] = s; sh1[w] = s2; }
    __syncthreads();
    if (w == 0) {
        float a  = lane < 8 ? sh0[lane] : 0.f;
        float b2 = lane < 8 ? sh1[lane] : 0.f;
        a = warpSum(a); b2 = warpSum(b2);
        if (lane == 0) {
            float mean = a * (1.f / Fn);
            float var  = b2 * (1.f / Fn) - mean * mean;
            bmean = mean;
            brstd = rsqrtf(var + 1e-5f);
        }
    }
    __syncthreads();
    float mean = bmean, rstd = brstd;
    #pragma unroll
    for (int i = 0; i < 4; i++) {
        int f = tid + i * 256;
        p[f] = (v[i] - mean) * rstd * g[f] + bta[f];
    }
}

// ---------------- host driver ----------------
static inline int cdiv(int a, int b) { return (a + b - 1) / b; }

extern "C" void kernel_launch(void* const* d_in, const int* in_sizes, int n_in,
                              void* d_out, int out_size) {
    const float* x     = (const float*)d_in[0];
    const float* proto = (const float*)d_in[1];
    const float* wq    = (const float*)d_in[2];
    const float* bq    = (const float*)d_in[3];
    const float* wk    = (const float*)d_in[4];
    const float* bk    = (const float*)d_in[5];
    const float* in_w  = (const float*)d_in[6];
    const float* in_b  = (const float*)d_in[7];
    const float* out_w = (const float*)d_in[8];
    const float* out_b = (const float*)d_in[9];
    const float* l1_w  = (const float*)d_in[10];
    const float* l1_b  = (const float*)d_in[11];
    const float* l2_w  = (const float*)d_in[12];
    const float* l2_b  = (const float*)d_in[13];
    const float* ln1_g = (const float*)d_in[14];
    const float* ln1_b = (const float*)d_in[15];
    const float* ln2_g = (const float*)d_in[16];
    const float* ln2_b = (const float*)d_in[17];
    const float* emb_w = (const float*)d_in[18];
    const float* emb_b = (const float*)d_in[19];
    float* out = (float*)d_out;

    float *src, *qkv, *ao, *tp, *ff, *wc3, *bc3, *wr;
    cudaGetSymbolAddress((void**)&src, g_src);
    cudaGetSymbolAddress((void**)&qkv, g_qkv);
    cudaGetSymbolAddress((void**)&ao,  g_ao);
    cudaGetSymbolAddress((void**)&tp,  g_t);
    cudaGetSymbolAddress((void**)&ff,  g_ff);
    cudaGetSymbolAddress((void**)&wc3, g_wc3);
    cudaGetSymbolAddress((void**)&bc3, g_bc3);
    cudaGetSymbolAddress((void**)&wr,  g_wr);

    static bool attr_done = false;
    if (!attr_done) {
        cudaFuncSetAttribute(flash_mma_kernel,
            cudaFuncAttributeMaxDynamicSharedMemorySize, FLASH_SMEM);
        cudaFuncSetAttribute(gemm_tb_async<0>,
            cudaFuncAttributeMaxDynamicSharedMemorySize, GEMM_SMEM);
        cudaFuncSetAttribute(gemm_tb_async<1>,
            cudaFuncAttributeMaxDynamicSharedMemorySize, GEMM_SMEM);
        cudaFuncSetAttribute(conv_mma_async,
            cudaFuncAttributeMaxDynamicSharedMemorySize, GEMM_SMEM);
        attr_done = true;
    }

    const int BS = Bn * Sn;                       // 8992
    const long FF = (long)Fn * Fn;
    const int MY = cdiv(BS, 128);                 // 71

    // 0) build src + reorder conv weights
    {
        long total = (long)Bn * Sn * Fn;
        build_src_kernel<<<(unsigned)((total + 255) / 256), 256>>>(x, proto, src);
        long wtot = (long)Fn * F3;
        reorder_conv_w<<<(unsigned)((wtot + 255) / 256), 256>>>(emb_w, wr);
    }

    // 1) build fused QKV weights/biases per layer
    for (int l = 0; l < Ln; l++) {
        const float* IW = in_w + (long)l * 3 * FF;
        const float* IB = in_b + (long)l * 3 * Fn;
        float* W3 = wc3 + (long)l * F3 * Fn;
        float* B3 = bc3 + (long)l * F3;
        dim3 g(8, 8);
        // WcQ = IW_q @ Wq ; WcK = IW_k @ Wk
        gemm_nt_kernel<<<g, 256>>>(IW, wq + (long)l * FF, W3,
                                   Fn, Fn, Fn, Fn, Fn, Fn);
        gemm_nt_kernel<<<g, 256>>>(IW + FF, wk + (long)l * FF, W3 + FF,
                                   Fn, Fn, Fn, Fn, Fn, Fn);
        bias_comb_kernel<<<Fn / 8, 256>>>(IW, bq + (long)l * Fn, IB, B3);
        bias_comb_kernel<<<Fn / 8, 256>>>(IW + FF, bk + (long)l * Fn, IB + Fn,
                                          B3 + Fn);
        cudaMemcpyAsync(W3 + 2 * FF, IW + 2 * FF, FF * sizeof(float),
                        cudaMemcpyDeviceToDevice);
        cudaMemcpyAsync(B3 + 2 * Fn, IB + 2 * Fn, Fn * sizeof(float),
                        cudaMemcpyDeviceToDevice);
    }

    for (int l = 0; l < Ln; l++) {
        const float* W3 = wc3 + (long)l * F3 * Fn;
        const float* B3 = bc3 + (long)l * F3;
        const float* OW = out_w + (long)l * FF;
        const float* OB = out_b + (long)l * Fn;
        const float* W1 = l1_w + (long)l * DFFn * Fn;
        const float* B1 = l1_b + (long)l * DFFn;
        const float* W2 = l2_w + (long)l * Fn * DFFn;
        const float* B2 = l2_b + (long)l * Fn;

        // fused QKV projection: qkv = src @ W3^T + B3   (N = 3072)
        {
            dim3 g(F3 / 128, MY);
            gemm_tb_async<0><<<g, 256, GEMM_SMEM>>>(src, W3, B3, qkv,
                                                    BS, F3, Fn, Fn, Fn, F3);
        }
        // flash attention -> ao
        {
            dim3 g(cdiv(Sn, 128), Bn * Hn);
            flash_mma_kernel<<<g, 256, FLASH_SMEM>>>(qkv, ao);
        }
        // out-proj
        {
            dim3 g(Fn / 128, MY);
            gemm_tb_async<0><<<g, 256, GEMM_SMEM>>>(ao, OW, OB, tp,
                                                    BS, Fn, Fn, Fn, Fn, Fn);
        }
        add_ln_kernel<<<BS, 256>>>(src, tp, ln1_g + (long)l * Fn, ln1_b + (long)l * Fn);
        // ffn1 (relu)
        {
            dim3 g(1, MY);
            gemm_tb_async<1><<<g, 256, GEMM_SMEM>>>(src, W1, B1, ff,
                                                    BS, DFFn, Fn, Fn, Fn, DFFn);
        }
        // ffn2
        {
            dim3 g(Fn / 128, MY);
            gemm_tb_async<0><<<g, 256, GEMM_SMEM>>>(ff, W2, B2, tp,
                                                    BS, Fn, DFFn, DFFn, DFFn, Fn);
        }
        add_ln_kernel<<<BS, 256>>>(src, tp, ln2_g + (long)l * Fn, ln2_b + (long)l * Fn);
    }

    // conv head
    {
        dim3 g(Tn / 128, Fn / 128, Bn);
        conv_mma_async<<<g, 256, GEMM_SMEM>>>(src, wr, emb_b, out);
    }
    (void)in_sizes; (void)n_in; (void)out_size;
}